// round 16
// baseline (speedup 1.0000x reference)
#include <cuda_runtime.h>
#include <cuda_bf16.h>
#include <cstdint>

// Problem constants
#define BATCH 8
#define CDIM  128
#define NPOS  2304              // H*W = 48*48
#define TM    128               // CTA tile M (y rows)
#define TN    64                // CTA tile N (x cols)
#define NL    6                 // n-tiles per CTA (A reused across them)
#define MT_M  (NPOS / TM)       // 18
#define MT_NS (NPOS / (TN*NL))  // 6 n-strips
#define SW    68                // SMEM row stride in 32-bit words (64 + 4 pad)
#define NTHREADS 256
#define KPW   64                // bf16x2 words per position row (CDIM/2)

// ---------------------------------------------------------------------------
// Scratch: squared norms + pre-converted bf16 transposed copies
// g_xbf/g_ybf layout: [b][pos][kp]  (row = 64 uint32 = 256 B, 16B-aligned)
// ---------------------------------------------------------------------------
__device__ float g_sx[BATCH * NPOS];
__device__ float g_sy[BATCH * NPOS];
__device__ uint4 g_xbf[BATCH * NPOS * (KPW / 4)];
__device__ uint4 g_ybf[BATCH * NPOS * (KPW / 4)];

__device__ __forceinline__ uint32_t pack_bf16x2(float lo, float hi) {
    __nv_bfloat162 p = __floats2bfloat162_rn(lo, hi);   // .x = lo (lower k)
    return *reinterpret_cast<uint32_t*>(&p);
}

// ---------------------------------------------------------------------------
// Kernel 1: norms (fp32 exact) + bf16 transpose-convert, SMEM tile transpose.
// (unchanged from R13 — measured ~9 us)
// ---------------------------------------------------------------------------
#define TPOS 32
#define TSW  129

__global__ __launch_bounds__(256)
void pwd_norms_kernel(const float* __restrict__ x,
                      const float* __restrict__ y) {
    __shared__ float xs[TPOS * TSW];
    __shared__ float ys[TPOS * TSW];

    int t  = threadIdx.x;
    int n0 = blockIdx.x * TPOS;
    int b  = blockIdx.y;
    size_t bOff = (size_t)b * CDIM * NPOS + n0;

    {
        int n = t & 31;
        int c0 = t >> 5;
#pragma unroll
        for (int i = 0; i < 16; i++) {
            int c = i * 8 + c0;
            xs[n * TSW + c] = x[bOff + (size_t)c * NPOS + n];
            ys[n * TSW + c] = y[bOff + (size_t)c * NPOS + n];
        }
    }
    __syncthreads();

    {
        int n   = t >> 3;
        int sub = t & 7;
        const float* xr = xs + n * TSW + sub * 16;
        const float* yr = ys + n * TSW + sub * 16;
        float sx = 0.f, sy = 0.f;
#pragma unroll
        for (int c = 0; c < 16; c++) {
            float xv = xr[c], yv = yr[c];
            sx = fmaf(xv, xv, sx);
            sy = fmaf(yv, yv, sy);
        }
#pragma unroll
        for (int o = 4; o > 0; o >>= 1) {
            sx += __shfl_xor_sync(0xffffffffu, sx, o);
            sy += __shfl_xor_sync(0xffffffffu, sy, o);
        }
        if (sub == 0) {
            g_sx[b * NPOS + n0 + n] = sx;
            g_sy[b * NPOS + n0 + n] = sy;
        }
    }

    {
        uint32_t* xw = reinterpret_cast<uint32_t*>(g_xbf) + ((size_t)b * NPOS + n0) * KPW;
        uint32_t* yw = reinterpret_cast<uint32_t*>(g_ybf) + ((size_t)b * NPOS + n0) * KPW;
#pragma unroll
        for (int i = 0; i < 8; i++) {
            int wd = i * 256 + t;
            int n  = wd >> 6;
            int kp = wd & 63;
            const float* xr = xs + n * TSW + 2 * kp;
            const float* yr = ys + n * TSW + 2 * kp;
            xw[wd] = pack_bf16x2(xr[0], xr[1]);
            yw[wd] = pack_bf16x2(yr[0], yr[1]);
        }
    }
}

// ---------------------------------------------------------------------------
// PTX helpers
// ---------------------------------------------------------------------------
__device__ __forceinline__ uint32_t smem_to_u32(const void* smem_ptr) {
    uint32_t addr;
    asm("{ .reg .u64 tmp; cvta.to.shared.u64 tmp, %1; cvt.u32.u64 %0, tmp; }"
        : "=r"(addr) : "l"(smem_ptr));
    return addr;
}

__device__ __forceinline__ void cp_async16(uint32_t smem_addr, const void* gmem) {
    asm volatile("cp.async.cg.shared.global [%0], [%1], 16;"
                 :: "r"(smem_addr), "l"(gmem));
}
#define CP_ASYNC_COMMIT() asm volatile("cp.async.commit_group;")
#define CP_ASYNC_WAIT_ALL() asm volatile("cp.async.wait_group 0;" ::: "memory")

__device__ __forceinline__ void mma_bf16(
    float& d0, float& d1, float& d2, float& d3,
    uint32_t a0, uint32_t a1, uint32_t a2, uint32_t a3,
    uint32_t b0, uint32_t b1)
{
    asm volatile(
        "mma.sync.aligned.m16n8k16.row.col.f32.bf16.bf16.f32 "
        "{%0,%1,%2,%3}, {%4,%5,%6,%7}, {%8,%9}, {%0,%1,%2,%3};"
        : "+f"(d0), "+f"(d1), "+f"(d2), "+f"(d3)
        : "r"(a0), "r"(a1), "r"(a2), "r"(a3), "r"(b0), "r"(b1));
}

// ---------------------------------------------------------------------------
// Kernel 2: bf16 mma.sync GEMM. CTA 128x64 (8 warps of 32x32), 3 CTAs/SM,
// A reused over NL=6 n-tiles, cp.async double-buffered B staging,
// 2-slot syCol ring.
//   out[b,i,j] = sx[i] + sy[j] - 2 * (y_i . x_j)
// ---------------------------------------------------------------------------
__global__ __launch_bounds__(NTHREADS, 3)
void pwd_gemm_kernel(float* __restrict__ out) {
    extern __shared__ uint32_t dsm[];
    uint32_t* sA  = dsm;                       // 128 * 68 words
    uint32_t* sB0 = dsm + TM * SW;             // 64 * 68 words
    uint32_t* sB1 = sB0 + TN * SW;             // 64 * 68 words
    float* s_sxRow = (float*)(sB1 + TN * SW);  // 128 floats
    float* s_syCol = s_sxRow + TM;             // 2 * 64 floats (ring)
    uint32_t smu = smem_to_u32(dsm);

    int tid  = threadIdx.x;
    int lane = tid & 31;
    int w    = tid >> 5;
    int qid  = lane >> 2;   // 0..7
    int qtr  = lane & 3;    // 0..3
    int wm   = w >> 1;      // warp row 0..3 (32 rows each)
    int wn   = w & 1;       // warp col 0..1 (32 cols each)

    int m0     = blockIdx.y * TM;
    int nbase0 = blockIdx.x * (NL * TN);
    int b      = blockIdx.z;

    // chunk map: c16 = chunk col (16B units, 0..15), rq = row quotient 0..15
    int c16 = tid & 15;
    int rq  = tid >> 4;

    const uint4* ybf  = g_ybf + ((size_t)b * NPOS + m0) * (KPW / 4);
    const uint4* xbf0 = g_xbf + ((size_t)b * NPOS + nbase0) * (KPW / 4);

    // ---- prologue: async-stage A (8 chunks/thr) + B tile 0 (4 chunks/thr) ----
#pragma unroll
    for (int i = 0; i < 8; i++) {
        int m = i * 16 + rq;   // 0..127
        cp_async16(smu + (uint32_t)(m * SW + c16 * 4) * 4, ybf + m * 16 + c16);
    }
    uint32_t sB0u = smu + (uint32_t)(TM * SW) * 4;
    uint32_t sB1u = sB0u + (uint32_t)(TN * SW) * 4;
#pragma unroll
    for (int i = 0; i < 4; i++) {
        int n = i * 16 + rq;   // 0..63
        cp_async16(sB0u + (uint32_t)(n * SW + c16 * 4) * 4, xbf0 + n * 16 + c16);
    }
    CP_ASYNC_COMMIT();

    if (tid < TM) {
        s_sxRow[tid] = g_sx[b * NPOS + m0 + tid];
    } else if (tid < TM + TN) {
        s_syCol[tid - TM] = g_sy[b * NPOS + nbase0 + (tid - TM)];
    }
    CP_ASYNC_WAIT_ALL();
    __syncthreads();

    const uint32_t* pA = sA + (wm * 32 + qid) * SW + qtr;

    // ---- tile loop ----
    for (int t = 0; t < NL; t++) {
        int n0 = nbase0 + t * TN;
        const uint32_t* pB = ((t & 1) ? sB1 : sB0) + (wn * 32 + qid) * SW + qtr;

        // issue next tile's B staging + syCol ring slot (t+1)&1
        if (t < NL - 1) {
            uint32_t dstu = (t & 1) ? sB0u : sB1u;
            const uint4* xbfn = g_xbf + ((size_t)b * NPOS + n0 + TN) * (KPW / 4);
#pragma unroll
            for (int i = 0; i < 4; i++) {
                int n = i * 16 + rq;
                cp_async16(dstu + (uint32_t)(n * SW + c16 * 4) * 4, xbfn + n * 16 + c16);
            }
            CP_ASYNC_COMMIT();
            if (tid >= TM && tid < TM + TN) {
                s_syCol[((t + 1) & 1) * TN + (tid - TM)] =
                    g_sy[b * NPOS + (n0 + TN) + (tid - TM)];
            }
        }

        float acc[2][4][4];
#pragma unroll
        for (int mi = 0; mi < 2; mi++)
#pragma unroll
            for (int j = 0; j < 4; j++)
#pragma unroll
                for (int r = 0; r < 4; r++) acc[mi][j][r] = 0.f;

        // main loop: 8 k-steps of K=16; 16 LDS + 8 MMA per step
#pragma unroll
        for (int s = 0; s < 8; s++) {
            uint32_t af[2][4];
#pragma unroll
            for (int mi = 0; mi < 2; mi++) {
                af[mi][0] = pA[(mi * 16 + 0) * SW + s * 8];
                af[mi][1] = pA[(mi * 16 + 8) * SW + s * 8];
                af[mi][2] = pA[(mi * 16 + 0) * SW + s * 8 + 4];
                af[mi][3] = pA[(mi * 16 + 8) * SW + s * 8 + 4];
            }
#pragma unroll
            for (int j = 0; j < 4; j++) {
                uint32_t b0 = pB[j * 8 * SW + s * 8];
                uint32_t b1 = pB[j * 8 * SW + s * 8 + 4];
#pragma unroll
                for (int mi = 0; mi < 2; mi++) {
                    mma_bf16(acc[mi][j][0], acc[mi][j][1], acc[mi][j][2], acc[mi][j][3],
                             af[mi][0], af[mi][1], af[mi][2], af[mi][3], b0, b1);
                }
            }
        }

        // fused epilogue: P = sx[i] + sy[j] - 2*acc, float2 stores
        const float* syCur = s_syCol + (t & 1) * TN;
#pragma unroll
        for (int mi = 0; mi < 2; mi++) {
#pragma unroll
            for (int h = 0; h < 2; h++) {
                int r = wm * 32 + mi * 16 + h * 8 + qid;
                float sxv = s_sxRow[r];
                size_t rowOff = ((size_t)b * NPOS + m0 + r) * (size_t)NPOS + n0;
#pragma unroll
                for (int j = 0; j < 4; j++) {
                    int cb = wn * 32 + 8 * j + 2 * qtr;
                    float d0 = acc[mi][j][h * 2 + 0];
                    float d1 = acc[mi][j][h * 2 + 1];
                    float2 v;
                    v.x = syCur[cb + 0] + fmaf(-2.f, d0, sxv);
                    v.y = syCur[cb + 1] + fmaf(-2.f, d1, sxv);
                    *reinterpret_cast<float2*>(out + rowOff + cb) = v;
                }
            }
        }

        if (t < NL - 1) {
            CP_ASYNC_WAIT_ALL();   // B(t+1) landed
            __syncthreads();       // all warps done with sBc(t); B(t+1) visible
        }
    }
}

// ---------------------------------------------------------------------------
// Launch
// ---------------------------------------------------------------------------
extern "C" void kernel_launch(void* const* d_in, const int* in_sizes, int n_in,
                              void* d_out, int out_size) {
    const float* x = (const float*)d_in[0];
    const float* y = (const float*)d_in[1];
    float* out = (float*)d_out;

    // Kernel 1: norms + bf16 transpose-convert (SMEM tile transpose)
    dim3 g1(NPOS / TPOS, BATCH);
    pwd_norms_kernel<<<g1, 256>>>(x, y);

    // Kernel 2: tiled bf16 GEMM, cp.async staging, 3 CTAs/SM
    int smemBytes = (TM * SW + 2 * TN * SW + TM + 2 * TN) * 4;   // ~70 KB
    cudaFuncSetAttribute(pwd_gemm_kernel,
                         cudaFuncAttributeMaxDynamicSharedMemorySize, smemBytes);
    dim3 grid(MT_NS, MT_M, BATCH);
    pwd_gemm_kernel<<<grid, NTHREADS, smemBytes>>>(out);
}

// round 17
// speedup vs baseline: 1.0888x; 1.0888x over previous
#include <cuda_runtime.h>
#include <cuda_bf16.h>
#include <cstdint>

// Problem constants
#define BATCH 8
#define CDIM  128
#define NPOS  2304              // H*W = 48*48
#define TM    128               // CTA tile M (y rows)
#define TN    64                // CTA tile N (x cols)
#define NL    6                 // n-tiles per CTA (A reused across them)
#define MT_M  (NPOS / TM)       // 18
#define MT_NS (NPOS / (TN*NL))  // 6 n-strips
#define SW    68                // SMEM row stride in 32-bit words (64 + 4 pad)
#define NTHREADS 256
#define KPW   64                // bf16x2 words per position row (CDIM/2)

// ---------------------------------------------------------------------------
// Scratch: squared norms + pre-converted bf16 transposed copies
// g_xbf/g_ybf layout: [b][pos][kp]  (row = 64 uint32 = 256 B, 16B-aligned)
// ---------------------------------------------------------------------------
__device__ float g_sx[BATCH * NPOS];
__device__ float g_sy[BATCH * NPOS];
__device__ uint4 g_xbf[BATCH * NPOS * (KPW / 4)];
__device__ uint4 g_ybf[BATCH * NPOS * (KPW / 4)];

__device__ __forceinline__ uint32_t pack_bf16x2(float lo, float hi) {
    __nv_bfloat162 p = __floats2bfloat162_rn(lo, hi);   // .x = lo (lower k)
    return *reinterpret_cast<uint32_t*>(&p);
}

// ---------------------------------------------------------------------------
// Kernel 1: norms (fp32 exact) + bf16 transpose-convert, SMEM tile transpose.
// (unchanged — measured ~9 us)
// ---------------------------------------------------------------------------
#define TPOS 32
#define TSW  129

__global__ __launch_bounds__(256)
void pwd_norms_kernel(const float* __restrict__ x,
                      const float* __restrict__ y) {
    __shared__ float xs[TPOS * TSW];
    __shared__ float ys[TPOS * TSW];

    int t  = threadIdx.x;
    int n0 = blockIdx.x * TPOS;
    int b  = blockIdx.y;
    size_t bOff = (size_t)b * CDIM * NPOS + n0;

    {
        int n = t & 31;
        int c0 = t >> 5;
#pragma unroll
        for (int i = 0; i < 16; i++) {
            int c = i * 8 + c0;
            xs[n * TSW + c] = x[bOff + (size_t)c * NPOS + n];
            ys[n * TSW + c] = y[bOff + (size_t)c * NPOS + n];
        }
    }
    __syncthreads();

    {
        int n   = t >> 3;
        int sub = t & 7;
        const float* xr = xs + n * TSW + sub * 16;
        const float* yr = ys + n * TSW + sub * 16;
        float sx = 0.f, sy = 0.f;
#pragma unroll
        for (int c = 0; c < 16; c++) {
            float xv = xr[c], yv = yr[c];
            sx = fmaf(xv, xv, sx);
            sy = fmaf(yv, yv, sy);
        }
#pragma unroll
        for (int o = 4; o > 0; o >>= 1) {
            sx += __shfl_xor_sync(0xffffffffu, sx, o);
            sy += __shfl_xor_sync(0xffffffffu, sy, o);
        }
        if (sub == 0) {
            g_sx[b * NPOS + n0 + n] = sx;
            g_sy[b * NPOS + n0 + n] = sy;
        }
    }

    {
        uint32_t* xw = reinterpret_cast<uint32_t*>(g_xbf) + ((size_t)b * NPOS + n0) * KPW;
        uint32_t* yw = reinterpret_cast<uint32_t*>(g_ybf) + ((size_t)b * NPOS + n0) * KPW;
#pragma unroll
        for (int i = 0; i < 8; i++) {
            int wd = i * 256 + t;
            int n  = wd >> 6;
            int kp = wd & 63;
            const float* xr = xs + n * TSW + 2 * kp;
            const float* yr = ys + n * TSW + 2 * kp;
            xw[wd] = pack_bf16x2(xr[0], xr[1]);
            yw[wd] = pack_bf16x2(yr[0], yr[1]);
        }
    }
}

// ---------------------------------------------------------------------------
// PTX helpers
// ---------------------------------------------------------------------------
__device__ __forceinline__ uint32_t smem_to_u32(const void* smem_ptr) {
    uint32_t addr;
    asm("{ .reg .u64 tmp; cvta.to.shared.u64 tmp, %1; cvt.u32.u64 %0, tmp; }"
        : "=r"(addr) : "l"(smem_ptr));
    return addr;
}

__device__ __forceinline__ void cp_async16(uint32_t smem_addr, const void* gmem) {
    asm volatile("cp.async.cg.shared.global [%0], [%1], 16;"
                 :: "r"(smem_addr), "l"(gmem));
}
#define CP_ASYNC_COMMIT() asm volatile("cp.async.commit_group;")
#define CP_ASYNC_WAIT_ALL() asm volatile("cp.async.wait_group 0;" ::: "memory")

__device__ __forceinline__ void mma_bf16(
    float& d0, float& d1, float& d2, float& d3,
    uint32_t a0, uint32_t a1, uint32_t a2, uint32_t a3,
    uint32_t b0, uint32_t b1)
{
    asm volatile(
        "mma.sync.aligned.m16n8k16.row.col.f32.bf16.bf16.f32 "
        "{%0,%1,%2,%3}, {%4,%5,%6,%7}, {%8,%9}, {%0,%1,%2,%3};"
        : "+f"(d0), "+f"(d1), "+f"(d2), "+f"(d3)
        : "r"(a0), "r"(a1), "r"(a2), "r"(a3), "r"(b0), "r"(b1));
}

// ---------------------------------------------------------------------------
// Kernel 2: bf16 mma.sync GEMM. CTA 128x64 (8 warps of 32x32), 2 CTAs/SM.
// A fragments held RESIDENT in registers across all NL=6 n-tiles
// (af_all[8][2][4] = 64 regs) — mainloop LDS is B-only.
//   out[b,i,j] = sx[i] + sy[j] - 2 * (y_i . x_j)
// ---------------------------------------------------------------------------
__global__ __launch_bounds__(NTHREADS, 2)
void pwd_gemm_kernel(float* __restrict__ out) {
    extern __shared__ uint32_t dsm[];
    uint32_t* sA  = dsm;                       // 128 * 68 words
    uint32_t* sB0 = dsm + TM * SW;             // 64 * 68 words
    uint32_t* sB1 = sB0 + TN * SW;             // 64 * 68 words
    float* s_sxRow = (float*)(sB1 + TN * SW);  // 128 floats
    float* s_syCol = s_sxRow + TM;             // 2 * 64 floats (ring)
    uint32_t smu = smem_to_u32(dsm);

    int tid  = threadIdx.x;
    int lane = tid & 31;
    int w    = tid >> 5;
    int qid  = lane >> 2;   // 0..7
    int qtr  = lane & 3;    // 0..3
    int wm   = w >> 1;      // warp row 0..3 (32 rows each)
    int wn   = w & 1;       // warp col 0..1 (32 cols each)

    int m0     = blockIdx.y * TM;
    int nbase0 = blockIdx.x * (NL * TN);
    int b      = blockIdx.z;

    // chunk map: c16 = chunk col (16B units, 0..15), rq = row quotient 0..15
    int c16 = tid & 15;
    int rq  = tid >> 4;

    const uint4* ybf  = g_ybf + ((size_t)b * NPOS + m0) * (KPW / 4);
    const uint4* xbf0 = g_xbf + ((size_t)b * NPOS + nbase0) * (KPW / 4);

    // ---- prologue: async-stage A (8 chunks/thr) + B tile 0 (4 chunks/thr) ----
#pragma unroll
    for (int i = 0; i < 8; i++) {
        int m = i * 16 + rq;   // 0..127
        cp_async16(smu + (uint32_t)(m * SW + c16 * 4) * 4, ybf + m * 16 + c16);
    }
    uint32_t sB0u = smu + (uint32_t)(TM * SW) * 4;
    uint32_t sB1u = sB0u + (uint32_t)(TN * SW) * 4;
#pragma unroll
    for (int i = 0; i < 4; i++) {
        int n = i * 16 + rq;   // 0..63
        cp_async16(sB0u + (uint32_t)(n * SW + c16 * 4) * 4, xbf0 + n * 16 + c16);
    }
    CP_ASYNC_COMMIT();

    if (tid < TM) {
        s_sxRow[tid] = g_sx[b * NPOS + m0 + tid];
    } else if (tid < TM + TN) {
        s_syCol[tid - TM] = g_sy[b * NPOS + nbase0 + (tid - TM)];
    }
    CP_ASYNC_WAIT_ALL();
    __syncthreads();

    // ---- load ALL A fragments once; resident across the tile loop ----
    const uint32_t* pA = sA + (wm * 32 + qid) * SW + qtr;
    uint32_t af_all[8][2][4];
#pragma unroll
    for (int s = 0; s < 8; s++) {
#pragma unroll
        for (int mi = 0; mi < 2; mi++) {
            af_all[s][mi][0] = pA[(mi * 16 + 0) * SW + s * 8];
            af_all[s][mi][1] = pA[(mi * 16 + 8) * SW + s * 8];
            af_all[s][mi][2] = pA[(mi * 16 + 0) * SW + s * 8 + 4];
            af_all[s][mi][3] = pA[(mi * 16 + 8) * SW + s * 8 + 4];
        }
    }

    // ---- tile loop ----
    for (int t = 0; t < NL; t++) {
        int n0 = nbase0 + t * TN;
        const uint32_t* pB = ((t & 1) ? sB1 : sB0) + (wn * 32 + qid) * SW + qtr;

        // issue next tile's B staging + syCol ring slot (t+1)&1
        if (t < NL - 1) {
            uint32_t dstu = (t & 1) ? sB0u : sB1u;
            const uint4* xbfn = g_xbf + ((size_t)b * NPOS + n0 + TN) * (KPW / 4);
#pragma unroll
            for (int i = 0; i < 4; i++) {
                int n = i * 16 + rq;
                cp_async16(dstu + (uint32_t)(n * SW + c16 * 4) * 4, xbfn + n * 16 + c16);
            }
            CP_ASYNC_COMMIT();
            if (tid >= TM && tid < TM + TN) {
                s_syCol[((t + 1) & 1) * TN + (tid - TM)] =
                    g_sy[b * NPOS + (n0 + TN) + (tid - TM)];
            }
        }

        float acc[2][4][4];
#pragma unroll
        for (int mi = 0; mi < 2; mi++)
#pragma unroll
            for (int j = 0; j < 4; j++)
#pragma unroll
                for (int r = 0; r < 4; r++) acc[mi][j][r] = 0.f;

        // main loop: 8 k-steps of K=16; 8 LDS (B only) + 8 MMA per step
#pragma unroll
        for (int s = 0; s < 8; s++) {
#pragma unroll
            for (int j = 0; j < 4; j++) {
                uint32_t b0 = pB[j * 8 * SW + s * 8];
                uint32_t b1 = pB[j * 8 * SW + s * 8 + 4];
#pragma unroll
                for (int mi = 0; mi < 2; mi++) {
                    mma_bf16(acc[mi][j][0], acc[mi][j][1], acc[mi][j][2], acc[mi][j][3],
                             af_all[s][mi][0], af_all[s][mi][1],
                             af_all[s][mi][2], af_all[s][mi][3], b0, b1);
                }
            }
        }

        // fused epilogue: P = sx[i] + sy[j] - 2*acc, float2 stores
        const float* syCur = s_syCol + (t & 1) * TN;
#pragma unroll
        for (int mi = 0; mi < 2; mi++) {
#pragma unroll
            for (int h = 0; h < 2; h++) {
                int r = wm * 32 + mi * 16 + h * 8 + qid;
                float sxv = s_sxRow[r];
                size_t rowOff = ((size_t)b * NPOS + m0 + r) * (size_t)NPOS + n0;
#pragma unroll
                for (int j = 0; j < 4; j++) {
                    int cb = wn * 32 + 8 * j + 2 * qtr;
                    float d0 = acc[mi][j][h * 2 + 0];
                    float d1 = acc[mi][j][h * 2 + 1];
                    float2 v;
                    v.x = syCur[cb + 0] + fmaf(-2.f, d0, sxv);
                    v.y = syCur[cb + 1] + fmaf(-2.f, d1, sxv);
                    *reinterpret_cast<float2*>(out + rowOff + cb) = v;
                }
            }
        }

        if (t < NL - 1) {
            CP_ASYNC_WAIT_ALL();   // B(t+1) landed
            __syncthreads();       // all warps done with sBc(t); B(t+1) visible
        }
    }
}

// ---------------------------------------------------------------------------
// Launch
// ---------------------------------------------------------------------------
extern "C" void kernel_launch(void* const* d_in, const int* in_sizes, int n_in,
                              void* d_out, int out_size) {
    const float* x = (const float*)d_in[0];
    const float* y = (const float*)d_in[1];
    float* out = (float*)d_out;

    // Kernel 1: norms + bf16 transpose-convert (SMEM tile transpose)
    dim3 g1(NPOS / TPOS, BATCH);
    pwd_norms_kernel<<<g1, 256>>>(x, y);

    // Kernel 2: tiled bf16 GEMM, A-fragments register-resident, 2 CTAs/SM
    int smemBytes = (TM * SW + 2 * TN * SW + TM + 2 * TN) * 4;   // ~70 KB
    cudaFuncSetAttribute(pwd_gemm_kernel,
                         cudaFuncAttributeMaxDynamicSharedMemorySize, smemBytes);
    dim3 grid(MT_NS, MT_M, BATCH);
    pwd_gemm_kernel<<<grid, NTHREADS, smemBytes>>>(out);
}